// round 15
// baseline (speedup 1.0000x reference)
#include <cuda_runtime.h>

#define NEG 1e30f

namespace {
constexpr int Bsz = 8;
constexpr int Npat = 196;
constexpr int D   = 128;
constexpr int DFF = 256;
constexpr int Cls = 1000;
constexpr int Mrows = Bsz * Npat;          // 1568
constexpr long MD    = (long)Mrows * D;    // 200704
constexpr long MDFF  = (long)Mrows * DFF;  // 401408
constexpr long NpD   = (long)Npat * D;
constexpr long NpN   = (long)Npat * Npat;
}

// ---------------- scratch ----------------
__device__ float g_h   [Mrows * D];
__device__ float g_xn  [Mrows * D];
__device__ float g_qkv [3 * Mrows * D];           // q,k,v (no splits)
__device__ float g_sc  [2 * Bsz * Npat * Npat];   // 2 K-split partials
__device__ float g_attn[4 * Mrows * D];           // embed(4)/attn(2) partials
__device__ float g_ffh [2 * Mrows * DFF];
__device__ float g_ffo [2 * Mrows * D];
__device__ float g_pool[Bsz * D];

// ---------------- packed f32x2 helpers (sm_100+) ----------------------------
__device__ __forceinline__ unsigned long long pack2(float a) {
    unsigned long long r;
    asm("mov.b64 %0, {%1, %1};" : "=l"(r) : "f"(a));
    return r;
}
// (aclo, achi) = max((aclo, achi), a2 + b2)  -- packed add, scalar maxes
__device__ __forceinline__ void addmax2(float& aclo, float& achi,
                                        unsigned long long a2, unsigned long long b2) {
    asm("{\n\t"
        ".reg .b64 t;\n\t"
        ".reg .f32 l, h;\n\t"
        "add.rn.f32x2 t, %2, %3;\n\t"
        "mov.b64 {l, h}, t;\n\t"
        "max.f32 %0, %0, l;\n\t"
        "max.f32 %1, %1, h;\n\t"
        "}" : "+f"(aclo), "+f"(achi) : "l"(a2), "l"(b2));
}

// ======== tropical GEMM: 32x64 tile, 128 thr, 4x4/thread, double-buffer =====
// C[m,n] = max_k (A[m,k] + B)     BMODE0: B[n*K+k]; BMODE1: B[k*Nc+n]
// PATCH: A read from raw image (patchify fused; kChunk mult of 16)
// KSPLIT: blockIdx.z = batch*KSPLIT + s; split s covers k in [s*kChunk, ...)
// ACMB/BCMB: combine that many upstream K-split partials (strides aPart/bPart)
// epi: 0 none, 1 +pos[(gm%196)*Nc+gn], 2 max with epi_ptr[0]
template<int BMODE, int PATCH, int KSPLIT, int ACMB, int BCMB>
__global__ __launch_bounds__(128)
void trop_gemm(const float* __restrict__ A,
               const float* __restrict__ b0, const float* __restrict__ b1,
               const float* __restrict__ b2,
               float* __restrict__ Cm,
               int Mr, int Nc, int K,
               long aStride, long bStride, long cStride, long splitStride,
               long aPart, long bPart,
               int kChunk, int epi, const float* __restrict__ epi_ptr)
{
    const int z = blockIdx.z;
    const int batch = (KSPLIT == 1) ? z : z / KSPLIT;
    const int s     = (KSPLIT == 1) ? 0 : z % KSPLIT;
    const int kBase = s * kChunk;
    const int kLen  = min(K - kBase, kChunk);

    const float* Bm = b1 ? (batch == 0 ? b0 : (batch == 1 ? b1 : b2))
                         : b0 + (long)batch * bStride;
    Cm += (long)batch * cStride + (long)s * splitStride;

    __shared__ float As[2][16][32];
    __shared__ float Bs[2][16][64];

    const int bm = blockIdx.x * 32;
    const int bn = blockIdx.y * 64;
    const int tid = threadIdx.x;
    const int ty = tid >> 4;
    const int tx = tid & 15;

    // ---- A staging: 1 float4 per thread (x ACMB partials) ----
    const int a_row = tid & 31;
    const int a_k   = (tid >> 5) << 2;
    const int gm_a  = bm + a_row;
    const bool a_valid = (gm_a < Mr);
    const float* a_src;
    if (PATCH) {
        int b  = gm_a / 196, n = gm_a % 196;
        int gy = n / 14, gx = n % 14;
        a_src = A + (long)b * 224 * 224 + (long)(gy * 16 + (kBase >> 4)) * 224 + gx * 16 + a_k;
    } else {
        a_src = A + (long)batch * aStride + (long)gm_a * K + kBase + a_k;
    }

    // ---- B staging ----
    const int b_n  = tid & 63;
    const int b_k8 = (tid >> 6) << 3;
    const bool b_valid0 = (bn + b_n) < Nc;
    const float* b_src0 = Bm + (long)(bn + b_n) * K + kBase + b_k8;
    const int b_k1 = tid >> 3;
    const int b_n8 = (tid & 7) << 3;
    const float* b_src1 = Bm + (long)(kBase + b_k1) * Nc + bn + b_n8;

    float acc[4][4];
#pragma unroll
    for (int i = 0; i < 4; i++)
#pragma unroll
        for (int j = 0; j < 4; j++) acc[i][j] = -NEG;

    const int ntiles = (kLen + 15) >> 4;

    float4 ra, rb0, rb1;
    auto fmax4 = [](float4& a, float4 b) {
        a.x = fmaxf(a.x, b.x); a.y = fmaxf(a.y, b.y);
        a.z = fmaxf(a.z, b.z); a.w = fmaxf(a.w, b.w);
    };
    auto gload = [&](int t) {
        const int k0 = t << 4;
        ra = rb0 = rb1 = make_float4(-NEG, -NEG, -NEG, -NEG);
        if (a_valid && (PATCH || (k0 + a_k < kLen))) {
            if (PATCH) {
                ra = *reinterpret_cast<const float4*>(a_src + t * 224);
            } else {
                ra = *reinterpret_cast<const float4*>(a_src + k0);
#pragma unroll
                for (int c = 1; c < ACMB; c++)
                    fmax4(ra, *reinterpret_cast<const float4*>(a_src + c * aPart + k0));
            }
        }
        if (BMODE == 0) {
            if (b_valid0) {
                if (k0 + b_k8 < kLen) {
                    rb0 = *reinterpret_cast<const float4*>(b_src0 + k0);
#pragma unroll
                    for (int c = 1; c < BCMB; c++)
                        fmax4(rb0, *reinterpret_cast<const float4*>(b_src0 + c * bPart + k0));
                }
                if (k0 + b_k8 + 4 < kLen) {
                    rb1 = *reinterpret_cast<const float4*>(b_src0 + k0 + 4);
#pragma unroll
                    for (int c = 1; c < BCMB; c++)
                        fmax4(rb1, *reinterpret_cast<const float4*>(b_src0 + c * bPart + k0 + 4));
                }
            }
        } else {
            if (k0 + b_k1 < kLen) {
                const float* p = b_src1 + (long)k0 * Nc;
                rb0 = *reinterpret_cast<const float4*>(p);
                rb1 = *reinterpret_cast<const float4*>(p + 4);
#pragma unroll
                for (int c = 1; c < BCMB; c++) {
                    fmax4(rb0, *reinterpret_cast<const float4*>(p + c * bPart));
                    fmax4(rb1, *reinterpret_cast<const float4*>(p + c * bPart + 4));
                }
            }
        }
    };
    auto sts = [&](int buf) {
        As[buf][a_k + 0][a_row] = ra.x;
        As[buf][a_k + 1][a_row] = ra.y;
        As[buf][a_k + 2][a_row] = ra.z;
        As[buf][a_k + 3][a_row] = ra.w;
        if (BMODE == 0) {
            Bs[buf][b_k8 + 0][b_n] = rb0.x;
            Bs[buf][b_k8 + 1][b_n] = rb0.y;
            Bs[buf][b_k8 + 2][b_n] = rb0.z;
            Bs[buf][b_k8 + 3][b_n] = rb0.w;
            Bs[buf][b_k8 + 4][b_n] = rb1.x;
            Bs[buf][b_k8 + 5][b_n] = rb1.y;
            Bs[buf][b_k8 + 6][b_n] = rb1.z;
            Bs[buf][b_k8 + 7][b_n] = rb1.w;
        } else {
            *reinterpret_cast<float4*>(&Bs[buf][b_k1][b_n8])     = rb0;
            *reinterpret_cast<float4*>(&Bs[buf][b_k1][b_n8 + 4]) = rb1;
        }
    };

    gload(0);
    sts(0);
    __syncthreads();

    for (int t = 0; t < ntiles; t++) {
        const int cur = t & 1;
        const bool more = (t + 1 < ntiles);
        if (more) gload(t + 1);

#pragma unroll
        for (int kk = 0; kk < 16; kk++) {
            float4 av = *reinterpret_cast<const float4*>(&As[cur][kk][ty << 2]);
            const unsigned long long* bp =
                reinterpret_cast<const unsigned long long*>(&Bs[cur][kk][tx << 2]);
            unsigned long long b01 = bp[0];
            unsigned long long b23 = bp[1];
            unsigned long long a0 = pack2(av.x);
            unsigned long long a1 = pack2(av.y);
            unsigned long long a2p = pack2(av.z);
            unsigned long long a3 = pack2(av.w);
            addmax2(acc[0][0], acc[0][1], a0,  b01);
            addmax2(acc[0][2], acc[0][3], a0,  b23);
            addmax2(acc[1][0], acc[1][1], a1,  b01);
            addmax2(acc[1][2], acc[1][3], a1,  b23);
            addmax2(acc[2][0], acc[2][1], a2p, b01);
            addmax2(acc[2][2], acc[2][3], a2p, b23);
            addmax2(acc[3][0], acc[3][1], a3,  b01);
            addmax2(acc[3][2], acc[3][3], a3,  b23);
        }
        if (more) { sts((t + 1) & 1); __syncthreads(); }
    }

    const float tauv = (epi == 2) ? epi_ptr[0] : 0.f;
#pragma unroll
    for (int i = 0; i < 4; i++) {
        int gm = bm + (ty << 2) + i;
        if (gm >= Mr) continue;
        int gn = bn + (tx << 2);
        if (gn >= Nc) continue;
        float4 v = make_float4(acc[i][0], acc[i][1], acc[i][2], acc[i][3]);
        if (epi == 1) {
            float4 p = *reinterpret_cast<const float4*>(&epi_ptr[(long)(gm % 196) * Nc + gn]);
            v.x += p.x; v.y += p.y; v.z += p.z; v.w += p.w;
        } else if (epi == 2) {
            v.x = fmaxf(v.x, tauv); v.y = fmaxf(v.y, tauv);
            v.z = fmaxf(v.z, tauv); v.w = fmaxf(v.w, tauv);
        }
        *reinterpret_cast<float4*>(Cm + (long)gm * Nc + gn) = v;
    }
}

// ------ embed combine: h = max of CNT partials; xn = pnorm(h) ---------------
template<int CNT>
__global__ void embed_combineN(const float* __restrict__ A, long stride,
                               float* __restrict__ H, float* __restrict__ XN, int rows) {
    int row = blockIdx.x * 8 + (threadIdx.x >> 5);
    if (row >= rows) return;
    int lane = threadIdx.x & 31;
    long off = (long)row * D;
    float4 a = reinterpret_cast<const float4*>(A + off)[lane];
#pragma unroll
    for (int c = 1; c < CNT; c++) {
        float4 b = reinterpret_cast<const float4*>(A + c * stride + off)[lane];
        a.x = fmaxf(a.x, b.x); a.y = fmaxf(a.y, b.y);
        a.z = fmaxf(a.z, b.z); a.w = fmaxf(a.w, b.w);
    }
    reinterpret_cast<float4*>(H + off)[lane] = a;
    float m = fmaxf(fmaxf(a.x, a.y), fmaxf(a.z, a.w));
#pragma unroll
    for (int o = 16; o; o >>= 1) m = fmaxf(m, __shfl_xor_sync(0xffffffffu, m, o));
    float4 r = make_float4(a.x - m, a.y - m, a.z - m, a.w - m);
    reinterpret_cast<float4*>(XN + off)[lane] = r;
}

// - residualN: a = max of CNT partials; h = max(h, pnorm(a)); opt xn=pnorm(h) -
template<int CNT>
__global__ void residualN(const float* __restrict__ A, long stride,
                          float* __restrict__ H, float* __restrict__ XN, int rows) {
    int row = blockIdx.x * 8 + (threadIdx.x >> 5);
    if (row >= rows) return;
    int lane = threadIdx.x & 31;
    long off = (long)row * D;
    float4 a = reinterpret_cast<const float4*>(A + off)[lane];
#pragma unroll
    for (int c = 1; c < CNT; c++) {
        float4 b = reinterpret_cast<const float4*>(A + c * stride + off)[lane];
        a.x = fmaxf(a.x, b.x); a.y = fmaxf(a.y, b.y);
        a.z = fmaxf(a.z, b.z); a.w = fmaxf(a.w, b.w);
    }
    float m = fmaxf(fmaxf(a.x, a.y), fmaxf(a.z, a.w));
#pragma unroll
    for (int o = 16; o; o >>= 1) m = fmaxf(m, __shfl_xor_sync(0xffffffffu, m, o));
    float4 h = reinterpret_cast<const float4*>(H + off)[lane];
    h.x = fmaxf(h.x, a.x - m); h.y = fmaxf(h.y, a.y - m);
    h.z = fmaxf(h.z, a.z - m); h.w = fmaxf(h.w, a.w - m);
    reinterpret_cast<float4*>(H + off)[lane] = h;
    if (XN) {
        float m2 = fmaxf(fmaxf(h.x, h.y), fmaxf(h.z, h.w));
#pragma unroll
        for (int o = 16; o; o >>= 1) m2 = fmaxf(m2, __shfl_xor_sync(0xffffffffu, m2, o));
        float4 r = make_float4(h.x - m2, h.y - m2, h.z - m2, h.w - m2);
        reinterpret_cast<float4*>(XN + off)[lane] = r;
    }
}

// ---------------- global tropical pool over patches -------------------------
__global__ void pool_kernel(const float* __restrict__ H, float* __restrict__ Pl) {
    int b = blockIdx.x, d = threadIdx.x;
    float m = -NEG;
    const float* p = H + (long)b * Npat * D + d;
    for (int n = 0; n < Npat; n++) m = fmaxf(m, p[n * D]);
    Pl[b * D + d] = m;
}

// ---------------- head ------------------------------------------------------
__global__ void head_kernel(const float* __restrict__ Pl, const float* __restrict__ W,
                            const float* __restrict__ ls, float* __restrict__ out) {
    int w = blockIdx.x * 8 + (threadIdx.x >> 5);
    int lane = threadIdx.x & 31;
    int b = w / Cls, c = w % Cls;
    if (b >= Bsz) return;
    const float* p = Pl + b * D;
    const float* wr = W + (long)c * D;
    float m = -NEG;
#pragma unroll
    for (int k = 0; k < 4; k++) {
        int idx = lane + 32 * k;
        m = fmaxf(m, p[idx] + wr[idx]);
    }
#pragma unroll
    for (int o = 16; o; o >>= 1) m = fmaxf(m, __shfl_xor_sync(0xffffffffu, m, o));
    if (lane == 0) out[b * Cls + c] = m * ls[0];
}

// ---------------------------------------------------------------------------
extern "C" void kernel_launch(void* const* d_in, const int* in_sizes, int n_in,
                              void* d_out, int out_size) {
    const float* x       = (const float*)d_in[0];
    const float* embed_W = (const float*)d_in[1];
    const float* pos     = (const float*)d_in[2];
    const float* qW[2]  = {(const float*)d_in[3],  (const float*)d_in[9]};
    const float* kW[2]  = {(const float*)d_in[4],  (const float*)d_in[10]};
    const float* vW[2]  = {(const float*)d_in[5],  (const float*)d_in[11]};
    const float* f1W[2] = {(const float*)d_in[6],  (const float*)d_in[12]};
    const float* f2W[2] = {(const float*)d_in[7],  (const float*)d_in[13]};
    const float* tau[2] = {(const float*)d_in[8],  (const float*)d_in[14]};
    const float* headW  = (const float*)d_in[15];
    const float* ls     = (const float*)d_in[16];
    float* out = (float*)d_out;

    void *h, *xn, *qkv, *sc, *attn, *ffh, *ffo, *pool;
    cudaGetSymbolAddress(&h,    g_h);
    cudaGetSymbolAddress(&xn,   g_xn);
    cudaGetSymbolAddress(&qkv,  g_qkv);
    cudaGetSymbolAddress(&sc,   g_sc);
    cudaGetSymbolAddress(&attn, g_attn);
    cudaGetSymbolAddress(&ffh,  g_ffh);
    cudaGetSymbolAddress(&ffo,  g_ffo);
    cudaGetSymbolAddress(&pool, g_pool);

    float* fh    = (float*)h;
    float* fxn   = (float*)xn;
    float* fq    = (float*)qkv;
    float* fk    = fq + MD;
    float* fv    = fq + 2 * MD;
    float* fsc   = (float*)sc;
    float* fattn = (float*)attn;
    float* fffh  = (float*)ffh;
    float* fffo  = (float*)ffo;
    float* fpool = (float*)pool;

    // embed (patchify fused, K=256 split 4) -> 4 partials in g_attn
    trop_gemm<0, 1, 4, 1, 1><<<dim3(49, 2, 4), 128>>>(
        x, embed_W, nullptr, nullptr, fattn,
        Mrows, D, 256, 0, 0, 0, MD, 0, 0, 64, 1, pos);
    embed_combineN<4><<<196, 256>>>(fattn, MD, fh, fxn, Mrows);

    for (int l = 0; l < 2; l++) {
        // fused q/k/v, no K split -> single buffers (cheap downstream staging)
        trop_gemm<0, 0, 1, 1, 1><<<dim3(49, 2, 3), 128>>>(
            fxn, qW[l], kW[l], vW[l], fq,
            Mrows, D, D, 0, 0, MD, 0, 0, 0, D, 0, nullptr);

        // scores, K=128 split 2 -> 2 partials
        trop_gemm<0, 0, 2, 1, 1><<<dim3(7, 4, 16), 128>>>(
            fq, fk, nullptr, nullptr, fsc,
            Npat, Npat, D, NpD, NpD, NpN, (long)Bsz * NpN, 0, 0, 64, 0, nullptr);

        // attn-out: A = max of 2 score partials; K=196 split (112, 84)
        trop_gemm<1, 0, 2, 2, 1><<<dim3(7, 2, 16), 128>>>(
            fsc, fv, nullptr, nullptr, fattn,
            Npat, D, Npat, NpN, NpD, NpD, MD, (long)Bsz * NpN, 0, 112, 0, nullptr);

        residualN<2><<<196, 256>>>(fattn, MD, fh, fxn, Mrows);

        // ff1, K=128 split 2 -> 2 partials (tau epilogue distributes over max)
        trop_gemm<0, 0, 2, 1, 1><<<dim3(49, 4, 2), 128>>>(
            fxn, f1W[l], nullptr, nullptr, fffh,
            Mrows, DFF, D, 0, 0, 0, MDFF, 0, 0, 64, 2, tau[l]);

        // ff2: A = max of 2 ffh partials; K=256 split 2
        trop_gemm<0, 0, 2, 2, 1><<<dim3(49, 2, 2), 128>>>(
            fffh, f2W[l], nullptr, nullptr, fffo,
            Mrows, D, DFF, 0, 0, 0, MD, MDFF, 0, 128, 0, nullptr);

        residualN<2><<<196, 256>>>(fffo, MD, fh, (l == 0) ? fxn : nullptr, Mrows);
    }

    pool_kernel<<<Bsz, D>>>(fh, fpool);
    head_kernel<<<1000, 256>>>(fpool, headW, ls, out);
}